// round 12
// baseline (speedup 1.0000x reference)
#include <cuda_runtime.h>
#include <cuda_fp16.h>
#include <math.h>

#define N1 10000
#define N2 10000
#define F_IN 256
#define E_EDGES 480000
#define P_PAIRS 200000
#define HID 128
#define NHEAD 8
#define DH 16

// ---------------- scratch (device globals) ----------------
__device__ float g_h1[N1 * HID];
__device__ float g_h2[N2 * HID];
__device__ float g_q1[N1 * HID];
__device__ float g_q2[N2 * HID];
__device__ __half g_kv1[N1 * 2 * HID];   // [node][lane][k0..3 | v0..3] interleaved fp16
__device__ __half g_kv2[N2 * 2 * HID];
__device__ float g_f1[2 * N1 * HID];
__device__ float g_f2[2 * N2 * HID];
__device__ float g_agg1[N1 * HID];
__device__ float g_agg2[N2 * HID];
__device__ float g_bf[8][HID];
// packed tf32 weight fragments
__device__ unsigned g_pWin[2][F_IN * HID];
__device__ unsigned g_pQA[8][HID * HID];       // [l*4 + {0,1:Wq, 2,3:Wa}]
__device__ unsigned g_pWf[8][HID * HID];       // folded K1,K2,V1,V2 for both layers
__device__ int g_cnt[2][N1];
__device__ int g_off[2][N1 + 1];
__device__ int g_rank[2][E_EDGES];
__device__ int g_csr_src[2][E_EDGES];

// ---------------- arg structs ----------------
struct GemmArgs { const float* A; const unsigned* B; const float* bias;
                  const float* Hprev; const float* skipp; void* C;
                  int geluA; int epi; int cofs; };  // epi: 0 none,1 relu,2 skip,3 half->kv
struct GemmBatch { GemmArgs g[2]; };
struct QkvArgs { const float* A; const unsigned* Bq; const float* biasq; float* Cq;
                 const unsigned* Bk; const float* biask;
                 const unsigned* Bv; const float* biasv; __half* Ckv; };
struct QkvBatch { QkvArgs a[2]; };
struct FoldArgs { const float* W; const float* b; const float* rel; unsigned* Pf; float* bf; };
struct FoldBatch { FoldArgs f[8]; };
struct RepArgs { const float* W; unsigned* P; int K; };
struct RepBatch { RepArgs r[10]; };
struct AttnArgs { const float* q; const __half* kv;
                  const int* csr; const int* off; const float* prior; float* agg; };
struct AttnBatch { AttnArgs a[2]; };

__device__ __forceinline__ float gelu_tanh(float x) {
    const float c = 0.7978845608028654f;
    float t = tanhf(c * (x + 0.044715f * x * x * x));
    return 0.5f * x * (1.0f + t);
}

__device__ __forceinline__ unsigned to_tf32(float f) {
    unsigned u;
    asm("cvt.rna.tf32.f32 %0, %1;" : "=r"(u) : "f"(f));
    return u;
}

// packed B fragment index (value at k,n)
__device__ __forceinline__ int packB_idx(int k, int n) {
    int ch = k >> 5, k32 = k & 31;
    int ks = k32 >> 3, kr = k32 & 7;
    int reg = kr >> 2;
    int lane = ((n & 7) << 2) | (kr & 3);
    int nt = n >> 3, ntp = nt >> 1, ntl = nt & 1;
    int q = ntl * 2 + reg;
    return ch * 4096 + ((ks * 8 + ntp) * 32 + lane) * 4 + q;
}

// ---------------- CSR build ----------------
__global__ void hist2_kernel(const int* __restrict__ dst0, int* __restrict__ cnt0, int* __restrict__ rk0,
                             const int* __restrict__ dst1, int* __restrict__ cnt1, int* __restrict__ rk1,
                             int E) {
    int t = blockIdx.x * blockDim.x + threadIdx.x;
    if (t < E) rk0[t] = atomicAdd(cnt0 + dst0[t], 1);
    else if (t < 2 * E) rk1[t - E] = atomicAdd(cnt1 + dst1[t - E], 1);
}

// thread-coarsened single-pass scan: 1024 threads x 10 items
__global__ void scan2_kernel(const int* __restrict__ cnt0, int* __restrict__ off0,
                             const int* __restrict__ cnt1, int* __restrict__ off1, int n) {
    const int* cnt = blockIdx.x ? cnt1 : cnt0;
    int* off = blockIdx.x ? off1 : off0;
    __shared__ int warpsum[32];
    int tid = threadIdx.x, lane = tid & 31, wid = tid >> 5;
    int base = tid * 10;
    int loc[10];
    int s = 0;
#pragma unroll
    for (int j = 0; j < 10; j++) {
        int i = base + j;
        int v = (i < n) ? cnt[i] : 0;
        loc[j] = s;
        s += v;
    }
    // block exclusive scan of s
    int x = s;
#pragma unroll
    for (int o = 1; o < 32; o <<= 1) {
        int t2 = __shfl_up_sync(0xFFFFFFFFu, x, o);
        if (lane >= o) x += t2;
    }
    if (lane == 31) warpsum[wid] = x;
    __syncthreads();
    if (wid == 0) {
        int v = warpsum[lane];
        int y = v;
#pragma unroll
        for (int o = 1; o < 32; o <<= 1) {
            int t2 = __shfl_up_sync(0xFFFFFFFFu, y, o);
            if (lane >= o) y += t2;
        }
        warpsum[lane] = y;
    }
    __syncthreads();
    int add = (wid > 0) ? warpsum[wid - 1] : 0;
    int excl = x - s + add;   // exclusive prefix for this thread's block of 10
#pragma unroll
    for (int j = 0; j < 10; j++) {
        int i = base + j;
        if (i < n) off[i] = excl + loc[j];
    }
    if (tid == 1023) off[n] = excl + s;   // total (n=10000 <= 10240 so last thread covers tail)
}

__global__ void scatter2_kernel(const int* __restrict__ src0, const int* __restrict__ dst0,
                                const int* __restrict__ off0, const int* __restrict__ rk0,
                                int* __restrict__ csr0,
                                const int* __restrict__ src1, const int* __restrict__ dst1,
                                const int* __restrict__ off1, const int* __restrict__ rk1,
                                int* __restrict__ csr1, int E) {
    int t = blockIdx.x * blockDim.x + threadIdx.x;
    if (t < E) {
        csr0[off0[dst0[t]] + rk0[t]] = src0[t];
    } else if (t < 2 * E) {
        int e = t - E;
        csr1[off1[dst1[e]] + rk1[e]] = src1[e];
    }
}

// ---------------- repack plain weights -> tf32 fragment layout ----------------
__global__ void repack_kernel(RepBatch rb) {
    RepArgs ra = rb.r[blockIdx.y];
    int t = blockIdx.x * 256 + threadIdx.x;
    if (t >= ra.K * HID) return;
    int k = t >> 7, n = t & 127;
    ra.P[packB_idx(k, n)] = to_tf32(ra.W[k * HID + n]);
}

// ---------------- fold arel/mrel into projections, write packed tf32 (x8) ----------------
__global__ void fold_kernel(FoldBatch fb) {
    FoldArgs fa = fb.f[blockIdx.y];
    int t = blockIdx.x * blockDim.x + threadIdx.x;
    if (t >= HID * HID) return;
    int row = t >> 7;
    int col = t & 127;
    int h = col >> 4;
    int eo = col & 15;
    const float* relh = fa.rel + h * (DH * DH);
    const float* wrow = fa.W + row * HID + h * DH;
    float acc = 0.f;
#pragma unroll
    for (int d = 0; d < DH; d++) acc = fmaf(wrow[d], relh[d * DH + eo], acc);
    fa.Pf[packB_idx(row, col)] = to_tf32(acc);
    if (row == 0) {
        const float* brow = fa.b + h * DH;
        float accb = 0.f;
#pragma unroll
        for (int d = 0; d < DH; d++) accb = fmaf(brow[d], relh[d * DH + eo], accb);
        fa.bf[col] = accb;
    }
}

// ---- shared device helpers for GEMM kernels ----
#define MMA_PAIR(ACC0, ACC1, AF, BB) \
    asm volatile("mma.sync.aligned.m16n8k8.row.col.f32.tf32.tf32.f32 " \
                 "{%0,%1,%2,%3}, {%4,%5,%6,%7}, {%8,%9}, {%0,%1,%2,%3};" \
                 : "+f"((ACC0)[0]), "+f"((ACC0)[1]), "+f"((ACC0)[2]), "+f"((ACC0)[3]) \
                 : "r"((AF).x), "r"((AF).y), "r"((AF).z), "r"((AF).w), "r"((BB).x), "r"((BB).y)); \
    asm volatile("mma.sync.aligned.m16n8k8.row.col.f32.tf32.tf32.f32 " \
                 "{%0,%1,%2,%3}, {%4,%5,%6,%7}, {%8,%9}, {%0,%1,%2,%3};" \
                 : "+f"((ACC1)[0]), "+f"((ACC1)[1]), "+f"((ACC1)[2]), "+f"((ACC1)[3]) \
                 : "r"((AF).x), "r"((AF).y), "r"((AF).z), "r"((AF).w), "r"((BB).z), "r"((BB).w));

// ---------------- GEMM: tf32 mma.sync, 64x128 tile, staged A + packed-B cp.async ----------------
__global__ void __launch_bounds__(128, 4) gemm_kernel(GemmBatch batch, int M, int K) {
    GemmArgs ga = batch.g[blockIdx.y];
    const int geluA = ga.geluA;
    const int epi = ga.epi;

    __shared__ unsigned Af[2][2048];
    __shared__ unsigned Bs[2][4096];

    const int tid = threadIdx.x;
    const int lane = tid & 31;
    const int w = tid >> 5;
    const int m0 = blockIdx.x * 64;

    float acc[16][4];
#pragma unroll
    for (int i = 0; i < 16; i++)
#pragma unroll
        for (int j = 0; j < 4; j++) acc[i][j] = 0.f;

    const int nchunks = K >> 5;
    const int sa_row = tid >> 1;
    const int sa_cb = (tid & 1) << 4;
    const int sa_mtile = sa_row >> 4;
    const int sa_mr = sa_row & 15;

    unsigned sB0 = (unsigned)__cvta_generic_to_shared(&Bs[0][0]) + tid * 16;
    unsigned sB1 = (unsigned)__cvta_generic_to_shared(&Bs[1][0]) + tid * 16;
#define CPB(BUF, CH) do { \
        unsigned sb_ = (BUF) ? sB1 : sB0; \
        const uint4* gp_ = (const uint4*)(ga.B + (size_t)(CH) * 4096) + tid; \
        _Pragma("unroll") \
        for (int j_ = 0; j_ < 8; j_++) \
            asm volatile("cp.async.ca.shared.global [%0], [%1], 16;" \
                         :: "r"(sb_ + j_ * 2048), "l"(gp_ + j_ * 128) : "memory"); \
        asm volatile("cp.async.commit_group;" ::: "memory"); \
    } while (0)

    CPB(0, 0);

    for (int ch = 0; ch < nchunks; ch++) {
        int cur = ch & 1;
        {
            int grow = m0 + sa_row;
            const float* ap = ga.A + (size_t)grow * K + ch * 32 + sa_cb;
            bool ok = (grow < M);
#pragma unroll
            for (int q = 0; q < 4; q++) {
                float4 v = ok ? *(const float4*)(ap + q * 4) : make_float4(0.f, 0.f, 0.f, 0.f);
                if (geluA && ok) {
                    v.x = gelu_tanh(v.x); v.y = gelu_tanh(v.y);
                    v.z = gelu_tanh(v.z); v.w = gelu_tanh(v.w);
                }
                float fv[4] = {v.x, v.y, v.z, v.w};
#pragma unroll
                for (int e = 0; e < 4; e++) {
                    int c = sa_cb + q * 4 + e;
                    int kstep = c >> 3, kc = c & 7;
                    int fl = ((sa_mr & 7) << 2) + (kc & 3);
                    int reg = (sa_mr >> 3) + ((kc >> 2) << 1);
                    Af[cur][(((kstep << 2) + sa_mtile) * 32 + fl) * 4 + reg] = to_tf32(fv[e]);
                }
            }
        }
        if (ch + 1 < nchunks) {
            CPB(cur ^ 1, ch + 1);
            asm volatile("cp.async.wait_group 1;" ::: "memory");
        } else {
            asm volatile("cp.async.wait_group 0;" ::: "memory");
        }
        __syncthreads();

#pragma unroll
        for (int ks = 0; ks < 4; ks++) {
            uint4 af = *(const uint4*)&Af[cur][(((ks << 2) + w) * 32 + lane) * 4];
#pragma unroll
            for (int ntp = 0; ntp < 8; ntp++) {
                uint4 bb = *(const uint4*)&Bs[cur][((ks * 8 + ntp) * 32 + lane) * 4];
                MMA_PAIR(acc[2 * ntp], acc[2 * ntp + 1], af, bb);
            }
        }
        __syncthreads();
    }
#undef CPB

    const int gid = lane >> 2;
    const int tq = lane & 3;
    const int row0 = m0 + w * 16 + gid;
    float sg = 0.f;
    if (epi == 2) sg = 1.f / (1.f + __expf(-ga.skipp[0]));

#pragma unroll
    for (int nt = 0; nt < 16; nt++) {
        int n = nt * 8 + tq * 2;
        float b0v = ga.bias[n];
        float b1v = ga.bias[n + 1];
#pragma unroll
        for (int rsel = 0; rsel < 2; rsel++) {
            int row = row0 + rsel * 8;
            if (row >= M) continue;
            float o0 = acc[nt][rsel * 2 + 0] + b0v;
            float o1 = acc[nt][rsel * 2 + 1] + b1v;
            if (epi == 1) { o0 = fmaxf(o0, 0.f); o1 = fmaxf(o1, 0.f); }
            float* cp = (float*)ga.C + (size_t)row * HID + n;
            if (epi == 2) {
                float2 hp = *(const float2*)(ga.Hprev + (size_t)row * HID + n);
                o0 = sg * o0 + (1.f - sg) * hp.x;
                o1 = sg * o1 + (1.f - sg) * hp.y;
            }
            *(float2*)cp = make_float2(o0, o1);
        }
    }
}

// ---------------- fused QKV GEMM: A staged once (full K=128), 3 B streams ----------------
__global__ void __launch_bounds__(128, 2) gemm_qkv_kernel(QkvBatch batch, int M) {
    QkvArgs ga = batch.a[blockIdx.y];
    extern __shared__ unsigned smemq[];
    unsigned* Af = smemq;                  // 4 chunks x 2048 = 8192 (32KB)
    unsigned* Bs = smemq + 8192;           // 2 x 4096 (32KB)

    const int tid = threadIdx.x;
    const int lane = tid & 31;
    const int w = tid >> 5;
    const int m0 = blockIdx.x * 64;

    const int sa_row = tid >> 1;
    const int sa_cb = (tid & 1) << 4;
    const int sa_mtile = sa_row >> 4;
    const int sa_mr = sa_row & 15;

    const unsigned* Bp[3] = {ga.Bq, ga.Bk, ga.Bv};

    unsigned sB0 = (unsigned)__cvta_generic_to_shared(Bs) + tid * 16;
    unsigned sB1 = sB0 + 16384;
#define CPQ(BUF, IDX) do { \
        unsigned sb_ = (BUF) ? sB1 : sB0; \
        const uint4* gp_ = (const uint4*)(Bp[(IDX) >> 2] + (size_t)((IDX) & 3) * 4096) + tid; \
        _Pragma("unroll") \
        for (int j_ = 0; j_ < 8; j_++) \
            asm volatile("cp.async.ca.shared.global [%0], [%1], 16;" \
                         :: "r"(sb_ + j_ * 2048), "l"(gp_ + j_ * 128) : "memory"); \
        asm volatile("cp.async.commit_group;" ::: "memory"); \
    } while (0)

    CPQ(0, 0);

    // ---- stage all of A (64 x 128) once ----
    {
        int grow = m0 + sa_row;
        bool ok = (grow < M);
        const float* arow = ga.A + (size_t)grow * HID;
#pragma unroll
        for (int ch = 0; ch < 4; ch++) {
            const float* ap = arow + ch * 32 + sa_cb;
#pragma unroll
            for (int q = 0; q < 4; q++) {
                float4 v = ok ? *(const float4*)(ap + q * 4) : make_float4(0.f, 0.f, 0.f, 0.f);
                float fv[4] = {v.x, v.y, v.z, v.w};
#pragma unroll
                for (int e = 0; e < 4; e++) {
                    int c = sa_cb + q * 4 + e;
                    int kstep = c >> 3, kc = c & 7;
                    int fl = ((sa_mr & 7) << 2) + (kc & 3);
                    int reg = (sa_mr >> 3) + ((kc >> 2) << 1);
                    Af[ch * 2048 + (((kstep << 2) + sa_mtile) * 32 + fl) * 4 + reg] = to_tf32(fv[e]);
                }
            }
        }
    }

    const int gid = lane >> 2;
    const int tq = lane & 3;
    const int row0 = m0 + w * 16 + gid;

    float acc[16][4];
#pragma unroll
    for (int i = 0; i < 16; i++)
#pragma unroll
        for (int j = 0; j < 4; j++) acc[i][j] = 0.f;

    for (int idx = 0; idx < 12; idx++) {
        int cur = idx & 1;
        int ch = idx & 3;
        int o = idx >> 2;
        if (idx + 1 < 12) {
            CPQ(cur ^ 1, idx + 1);
            asm volatile("cp.async.wait_group 1;" ::: "memory");
        } else {
            asm volatile("cp.async.wait_group 0;" ::: "memory");
        }
        __syncthreads();

        unsigned* bsrc = Bs + cur * 4096;
#pragma unroll
        for (int ks = 0; ks < 4; ks++) {
            uint4 af = *(const uint4*)&Af[ch * 2048 + (((ks << 2) + w) * 32 + lane) * 4];
#pragma unroll
            for (int ntp = 0; ntp < 8; ntp++) {
                uint4 bb = *(const uint4*)&bsrc[((ks * 8 + ntp) * 32 + lane) * 4];
                MMA_PAIR(acc[2 * ntp], acc[2 * ntp + 1], af, bb);
            }
        }

        if (ch == 3) {
            // epilogue for output o
            const float* bias = (o == 0) ? ga.biasq : (o == 1) ? ga.biask : ga.biasv;
#pragma unroll
            for (int nt = 0; nt < 16; nt++) {
                int n = nt * 8 + tq * 2;
                float b0v = bias[n];
                float b1v = bias[n + 1];
#pragma unroll
                for (int rsel = 0; rsel < 2; rsel++) {
                    int row = row0 + rsel * 8;
                    if (row >= M) continue;
                    float o0 = acc[nt][rsel * 2 + 0] + b0v;
                    float o1 = acc[nt][rsel * 2 + 1] + b1v;
                    if (o == 0) {
                        *(float2*)(ga.Cq + (size_t)row * HID + n) = make_float2(o0, o1);
                    } else {
                        int cofs = (o == 1) ? 0 : 4;
                        __half* cp = ga.Ckv + (size_t)row * 256 + ((n >> 2) << 3) + (n & 3) + cofs;
                        *(__half2*)cp = __floats2half2_rn(o0, o1);
                    }
                }
            }
#pragma unroll
            for (int i = 0; i < 16; i++)
#pragma unroll
                for (int j = 0; j < 4; j++) acc[i][j] = 0.f;
        }
        __syncthreads();
    }
#undef CPQ
}

// ---------------- attention: warp/dst, online softmax, interleaved fp16 kv ----------------
__device__ __forceinline__ void ld_kv8(const __half* kvbase, int lane, float* k4, float* v4) {
    uint4 u = ((const uint4*)kvbase)[lane];
    float2 a = __half22float2(*(__half2*)&u.x);
    float2 b = __half22float2(*(__half2*)&u.y);
    float2 c = __half22float2(*(__half2*)&u.z);
    float2 d = __half22float2(*(__half2*)&u.w);
    k4[0] = a.x; k4[1] = a.y; k4[2] = b.x; k4[3] = b.y;
    v4[0] = c.x; v4[1] = c.y; v4[2] = d.x; v4[3] = d.y;
}

__global__ void __launch_bounds__(256) attn_kernel(AttnBatch ab, int n) {
    AttnArgs aa = ab.a[blockIdx.y];
    int node = blockIdx.x * 8 + (threadIdx.x >> 5);
    if (node >= n) return;
    int lane = threadIdx.x & 31;
    int h = lane >> 2;

    int beg = aa.off[node];
    int end = aa.off[node + 1];
    float4 qv = ((const float4*)(aa.q + (size_t)node * HID))[lane];
    float pr = aa.prior[h] * 0.25f;  // 1/sqrt(16)

    float m = -INFINITY, s = 0.f;
    float ax = 0.f, ay = 0.f, az = 0.f, aw = 0.f;

    int i = beg;
    for (; i + 3 < end; i += 4) {
        int sn0 = aa.csr[i], sn1 = aa.csr[i + 1], sn2 = aa.csr[i + 2], sn3 = aa.csr[i + 3];
        float kf[4][4], vf[4][4];
        ld_kv8(aa.kv + (size_t)sn0 * 256, lane, kf[0], vf[0]);
        ld_kv8(aa.kv + (size_t)sn1 * 256, lane, kf[1], vf[1]);
        ld_kv8(aa.kv + (size_t)sn2 * 256, lane, kf[2], vf[2]);
        ld_kv8(aa.kv + (size_t)sn3 * 256, lane, kf[3], vf[3]);
        float d[4];
#pragma unroll
        for (int j = 0; j < 4; j++)
            d[j] = qv.x * kf[j][0] + qv.y * kf[j][1] + qv.z * kf[j][2] + qv.w * kf[j][3];
#pragma unroll
        for (int j = 0; j < 4; j++) d[j] += __shfl_xor_sync(0xFFFFFFFFu, d[j], 1);
#pragma unroll
        for (int j = 0; j < 4; j++) d[j] += __shfl_xor_sync(0xFFFFFFFFu, d[j], 2);
        float lg0 = d[0] * pr, lg1 = d[1] * pr, lg2 = d[2] * pr, lg3 = d[3] * pr;
        float nm = fmaxf(fmaxf(m, fmaxf(lg0, lg1)), fmaxf(lg2, lg3));
        float c = __expf(m - nm);
        float w0 = __expf(lg0 - nm);
        float w1 = __expf(lg1 - nm);
        float w2 = __expf(lg2 - nm);
        float w3 = __expf(lg3 - nm);
        m = nm;
        s = s * c + w0 + w1 + w2 + w3;
        ax = ax * c + w0 * vf[0][0] + w1 * vf[1][0] + w2 * vf[2][0] + w3 * vf[3][0];
        ay = ay * c + w0 * vf[0][1] + w1 * vf[1][1] + w2 * vf[2][1] + w3 * vf[3][1];
        az = az * c + w0 * vf[0][2] + w1 * vf[1][2] + w2 * vf[2][2] + w3 * vf[3][2];
        aw = aw * c + w0 * vf[0][3] + w1 * vf[1][3] + w2 * vf[2][3] + w3 * vf[3][3];
    }
    for (; i < end; i++) {
        int sn = aa.csr[i];
        float kv[4], vv[4];
        ld_kv8(aa.kv + (size_t)sn * 256, lane, kv, vv);
        float d = qv.x * kv[0] + qv.y * kv[1] + qv.z * kv[2] + qv.w * kv[3];
        d += __shfl_xor_sync(0xFFFFFFFFu, d, 1);
        d += __shfl_xor_sync(0xFFFFFFFFu, d, 2);
        float lg = d * pr;
        float nm = fmaxf(m, lg);
        float c = __expf(m - nm);
        float w = __expf(lg - nm);
        m = nm;
        s = s * c + w;
        ax = ax * c + w * vv[0];
        ay = ay * c + w * vv[1];
        az = az * c + w * vv[2];
        aw = aw * c + w * vv[3];
    }
    float inv = 1.f / (s + 1e-16f);
    ((float4*)(aa.agg + (size_t)node * HID))[lane] = make_float4(ax * inv, ay * inv, az * inv, aw * inv);
}

// ---------------- pair scoring ----------------
__global__ void pred_kernel(const float* __restrict__ f1a, const float* __restrict__ f1b,
                            const float* __restrict__ f2a, const float* __restrict__ f2b,
                            const int* __restrict__ mi, const int* __restrict__ di,
                            float* __restrict__ out, int P) {
    int gw = (blockIdx.x * blockDim.x + threadIdx.x) >> 5;
    int lane = threadIdx.x & 31;
    if (gw >= P) return;
    int mm = mi[gw];
    int dd = di[gw];
    float4 a0 = ((const float4*)(f1a + (size_t)mm * HID))[lane];
    float4 b0 = ((const float4*)(f2a + (size_t)dd * HID))[lane];
    float4 a1 = ((const float4*)(f1b + (size_t)mm * HID))[lane];
    float4 b1 = ((const float4*)(f2b + (size_t)dd * HID))[lane];
    float acc = a0.x * b0.x + a0.y * b0.y + a0.z * b0.z + a0.w * b0.w
              + a1.x * b1.x + a1.y * b1.y + a1.z * b1.z + a1.w * b1.w;
#pragma unroll
    for (int o = 16; o > 0; o >>= 1) acc += __shfl_xor_sync(0xFFFFFFFFu, acc, o);
    if (lane == 0) out[gw] = acc;
}

// ---------------- host orchestration ----------------
extern "C" void kernel_launch(void* const* d_in, const int* in_sizes, int n_in,
                              void* d_out, int out_size) {
    const float* x1    = (const float*)d_in[0];
    const float* x2    = (const float*)d_in[1];
    const int*   ei12  = (const int*)d_in[2];
    const int*   ei21  = (const int*)d_in[3];
    const int*   epair = (const int*)d_in[4];
    const float* Win1  = (const float*)d_in[5];
    const float* bin1  = (const float*)d_in[6];
    const float* Win2  = (const float*)d_in[7];
    const float* bin2  = (const float*)d_in[8];
    const float* Wk    = (const float*)d_in[9];
    const float* bk    = (const float*)d_in[10];
    const float* Wq    = (const float*)d_in[11];
    const float* bq    = (const float*)d_in[12];
    const float* Wv    = (const float*)d_in[13];
    const float* bv    = (const float*)d_in[14];
    const float* Wa    = (const float*)d_in[15];
    const float* ba    = (const float*)d_in[16];
    const float* skip  = (const float*)d_in[17];
    const float* arel  = (const float*)d_in[18];
    const float* mrel  = (const float*)d_in[19];
    const float* prior = (const float*)d_in[20];
    float* out = (float*)d_out;

    void* p;
#define SYMF(var, sym) cudaGetSymbolAddress(&p, sym); float* var = (float*)p;
#define SYMH(var, sym) cudaGetSymbolAddress(&p, sym); __half* var = (__half*)p;
#define SYMI(var, sym) cudaGetSymbolAddress(&p, sym); int* var = (int*)p;
#define SYMU(var, sym) cudaGetSymbolAddress(&p, sym); unsigned* var = (unsigned*)p;
    SYMF(h1, g_h1) SYMF(h2, g_h2)
    SYMF(q1, g_q1) SYMF(q2, g_q2)
    SYMH(kv1, g_kv1) SYMH(kv2, g_kv2)
    SYMF(f1, g_f1) SYMF(f2, g_f2)
    SYMF(agg1, g_agg1) SYMF(agg2, g_agg2)
    SYMF(bfbase, g_bf)
    SYMU(pWin, g_pWin) SYMU(pQA, g_pQA) SYMU(pWf, g_pWf)
    SYMI(cnt, g_cnt) SYMI(off, g_off) SYMI(rnk, g_rank) SYMI(csr, g_csr_src)
#undef SYMF
#undef SYMH
#undef SYMI
#undef SYMU
    float* bf[8];
    unsigned* wfp[8];
    for (int i = 0; i < 8; i++) { wfp[i] = pWf + (size_t)i * HID * HID; bf[i] = bfbase + i * HID; }
    int* cnt12 = cnt;  int* cnt21 = cnt + N1;
    int* off12 = off;  int* off21 = off + (N1 + 1);
    int* rk12 = rnk;   int* rk21 = rnk + E_EDGES;
    int* csr12 = csr;  int* csr21 = csr + E_EDGES;

    const int GEMM_GRID = (N1 + 63) / 64;     // 157
    const int E2_BLOCKS = (2 * E_EDGES + 255) / 256;
    const int ATTN_GRID = (N1 + 7) / 8;
    const int PRED_BLOCKS = (P_PAIRS * 32 + 255) / 256;
    const int QKV_SMEM = 65536;

    cudaFuncSetAttribute(gemm_qkv_kernel, cudaFuncAttributeMaxDynamicSharedMemorySize, QKV_SMEM);

    // ---- repack static weights ----
    {
        RepBatch rb;
        rb.r[0] = {Win1, pWin, F_IN};
        rb.r[1] = {Win2, pWin + F_IN * HID, F_IN};
        for (int l = 0; l < 2; l++) {
            rb.r[2 + l * 4 + 0] = {Wq + (size_t)(l * 2 + 0) * HID * HID, pQA + (size_t)(l * 4 + 0) * HID * HID, HID};
            rb.r[2 + l * 4 + 1] = {Wq + (size_t)(l * 2 + 1) * HID * HID, pQA + (size_t)(l * 4 + 1) * HID * HID, HID};
            rb.r[2 + l * 4 + 2] = {Wa + (size_t)(l * 2 + 0) * HID * HID, pQA + (size_t)(l * 4 + 2) * HID * HID, HID};
            rb.r[2 + l * 4 + 3] = {Wa + (size_t)(l * 2 + 1) * HID * HID, pQA + (size_t)(l * 4 + 3) * HID * HID, HID};
        }
        repack_kernel<<<dim3(128, 10), 256>>>(rb);
    }

    // ---- fold both layers' K/V relation weights ----
    {
        FoldBatch fb;
        for (int l = 0; l < 2; l++) {
            const int i0 = l * 2 + 0, i1 = l * 2 + 1;
            fb.f[l * 4 + 0] = {Wk + (size_t)i0 * HID * HID, bk + (size_t)i0 * HID,
                               arel + (size_t)i0 * NHEAD * DH * DH, wfp[l * 4 + 0], bf[l * 4 + 0]};
            fb.f[l * 4 + 1] = {Wk + (size_t)i1 * HID * HID, bk + (size_t)i1 * HID,
                               arel + (size_t)i1 * NHEAD * DH * DH, wfp[l * 4 + 1], bf[l * 4 + 1]};
            fb.f[l * 4 + 2] = {Wv + (size_t)i0 * HID * HID, bv + (size_t)i0 * HID,
                               mrel + (size_t)i0 * NHEAD * DH * DH, wfp[l * 4 + 2], bf[l * 4 + 2]};
            fb.f[l * 4 + 3] = {Wv + (size_t)i1 * HID * HID, bv + (size_t)i1 * HID,
                               mrel + (size_t)i1 * NHEAD * DH * DH, wfp[l * 4 + 3], bf[l * 4 + 3]};
        }
        fold_kernel<<<dim3(64, 8), 256>>>(fb);
    }

    // ---- CSR build ----
    cudaMemsetAsync(cnt12, 0, (size_t)2 * N1 * 4);
    hist2_kernel<<<E2_BLOCKS, 256>>>(ei12 + E_EDGES, cnt12, rk12,
                                     ei21 + E_EDGES, cnt21, rk21, E_EDGES);
    scan2_kernel<<<2, 1024>>>(cnt12, off12, cnt21, off21, N1);
    scatter2_kernel<<<E2_BLOCKS, 256>>>(ei12, ei12 + E_EDGES, off12, rk12, csr12,
                                        ei21, ei21 + E_EDGES, off21, rk21, csr21, E_EDGES);

    // ---- input projections + relu ----
    {
        GemmBatch gb = {};
        gb.g[0] = {x1, pWin, bin1, nullptr, nullptr, h1, 0, 1, 0};
        gb.g[1] = {x2, pWin + F_IN * HID, bin2, nullptr, nullptr, h2, 0, 1, 0};
        gemm_kernel<<<dim3(GEMM_GRID, 2), 128>>>(gb, N1, F_IN);
    }

    const float* cur1 = h1;
    const float* cur2 = h2;

    for (int l = 0; l < 2; l++) {
        const int i0 = l * 2 + 0, i1 = l * 2 + 1;
        {
            QkvBatch qb;
            qb.a[0] = {cur1, pQA + (size_t)(l * 4 + 0) * HID * HID, bq + (size_t)i0 * HID, q1,
                       wfp[l * 4 + 0], bf[l * 4 + 0], wfp[l * 4 + 2], bf[l * 4 + 2], kv1};
            qb.a[1] = {cur2, pQA + (size_t)(l * 4 + 1) * HID * HID, bq + (size_t)i1 * HID, q2,
                       wfp[l * 4 + 1], bf[l * 4 + 1], wfp[l * 4 + 3], bf[l * 4 + 3], kv2};
            gemm_qkv_kernel<<<dim3(GEMM_GRID, 2), 128, QKV_SMEM>>>(qb, N1);
        }
        {
            AttnBatch ab;
            ab.a[0] = {q2, kv1, csr12, off12, prior + i0 * NHEAD, agg2};
            ab.a[1] = {q1, kv2, csr21, off21, prior + i1 * NHEAD, agg1};
            attn_kernel<<<dim3(ATTN_GRID, 2), 256>>>(ab, N1);
        }
        float* out1 = f1 + (size_t)l * N1 * HID;
        float* out2 = f2 + (size_t)l * N2 * HID;
        {
            GemmBatch gb = {};
            gb.g[0] = {agg1, pQA + (size_t)(l * 4 + 2) * HID * HID, ba + (size_t)i0 * HID, cur1, skip + i0, out1, 1, 2, 0};
            gb.g[1] = {agg2, pQA + (size_t)(l * 4 + 3) * HID * HID, ba + (size_t)i1 * HID, cur2, skip + i1, out2, 1, 2, 0};
            gemm_kernel<<<dim3(GEMM_GRID, 2), 128>>>(gb, N1, HID);
        }
        cur1 = out1;
        cur2 = out2;
    }

    pred_kernel<<<PRED_BLOCKS, 256>>>(f1, f1 + (size_t)N1 * HID,
                                      f2, f2 + (size_t)N2 * HID,
                                      epair, epair + P_PAIRS, out, P_PAIRS);
}

// round 13
// speedup vs baseline: 1.0760x; 1.0760x over previous
#include <cuda_runtime.h>
#include <cuda_fp16.h>
#include <math.h>

#define N1 10000
#define N2 10000
#define F_IN 256
#define E_EDGES 480000
#define P_PAIRS 200000
#define HID 128
#define NHEAD 8
#define DH 16

// ---------------- scratch (device globals) ----------------
__device__ float g_h1[N1 * HID];
__device__ float g_h2[N2 * HID];
__device__ float g_q1[N1 * HID];
__device__ float g_q2[N2 * HID];
__device__ __half g_kv1[N1 * 2 * HID];   // [node][lane][k0..3 | v0..3] interleaved fp16
__device__ __half g_kv2[N2 * 2 * HID];
__device__ float g_f1[2 * N1 * HID];
__device__ float g_f2[2 * N2 * HID];
__device__ float g_agg1[N1 * HID];
__device__ float g_agg2[N2 * HID];
__device__ float g_bf[8][HID];
// packed tf32 weight fragments
__device__ unsigned g_pWin[2][F_IN * HID];
__device__ unsigned g_pQA[8][HID * HID];       // [l*4 + {0,1:Wq, 2,3:Wa}]
__device__ unsigned g_pWf[8][HID * HID];       // folded K1,K2,V1,V2 for both layers
__device__ int g_cnt[2][N1];
__device__ int g_off[2][N1 + 1];
__device__ int g_rank[2][E_EDGES];
__device__ int g_csr_src[2][E_EDGES];

// ---------------- arg structs ----------------
struct GemmArgs { const float* A; const unsigned* B; const float* bias;
                  const float* Hprev; const float* skipp; void* C;
                  int geluA; int epi; int cofs; };  // epi: 0 none,1 relu,2 skip,3 half->kv
struct GemmBatch { GemmArgs g[6]; };
struct FoldArgs { const float* W; const float* b; const float* rel; unsigned* Pf; float* bf; };
struct FoldBatch { FoldArgs f[8]; };
struct RepArgs { const float* W; unsigned* P; int K; };
struct RepBatch { RepArgs r[10]; };
struct AttnArgs { const float* q; const __half* kv;
                  const int* csr; const int* off; const float* prior; float* agg; };
struct AttnBatch { AttnArgs a[2]; };

__device__ __forceinline__ float gelu_tanh(float x) {
    const float c = 0.7978845608028654f;
    float t = tanhf(c * (x + 0.044715f * x * x * x));
    return 0.5f * x * (1.0f + t);
}

__device__ __forceinline__ unsigned to_tf32(float f) {
    unsigned u;
    asm("cvt.rna.tf32.f32 %0, %1;" : "=r"(u) : "f"(f));
    return u;
}

// packed B fragment index (value at k,n)
__device__ __forceinline__ int packB_idx(int k, int n) {
    int ch = k >> 5, k32 = k & 31;
    int ks = k32 >> 3, kr = k32 & 7;
    int reg = kr >> 2;
    int lane = ((n & 7) << 2) | (kr & 3);
    int nt = n >> 3, ntp = nt >> 1, ntl = nt & 1;
    int q = ntl * 2 + reg;
    return ch * 4096 + ((ks * 8 + ntp) * 32 + lane) * 4 + q;
}

// ---------------- CSR build ----------------
__global__ void hist2_kernel(const int* __restrict__ dst0, int* __restrict__ cnt0, int* __restrict__ rk0,
                             const int* __restrict__ dst1, int* __restrict__ cnt1, int* __restrict__ rk1,
                             int E) {
    int t = blockIdx.x * blockDim.x + threadIdx.x;
    if (t < E) rk0[t] = atomicAdd(cnt0 + dst0[t], 1);
    else if (t < 2 * E) rk1[t - E] = atomicAdd(cnt1 + dst1[t - E], 1);
}

// thread-coarsened single-pass scan with coalesced smem staging (n <= 10240)
__global__ void scan2_kernel(const int* __restrict__ cnt0, int* __restrict__ off0,
                             const int* __restrict__ cnt1, int* __restrict__ off1, int n) {
    const int* cnt = blockIdx.x ? cnt1 : cnt0;
    int* off = blockIdx.x ? off1 : off0;
    __shared__ int sc[10240];
    __shared__ int warpsum[32];
    int tid = threadIdx.x, lane = tid & 31, wid = tid >> 5;
    // coalesced stage: 10240 ints = 2560 int4
    const int4* c4 = (const int4*)cnt;
#pragma unroll
    for (int j = 0; j < 3; j++) {
        int i = tid + j * 1024;
        if (i < 2500) ((int4*)sc)[i] = c4[i];
    }
    if (tid < n - 10000 + 240) { /* no-op placeholder keeps compiler honest */ }
    // zero the tail beyond n
    if (tid >= 784 && tid < 1024) sc[10000 + (tid - 784)] = 0;   // 10000..10239
    __syncthreads();

    int base = tid * 10;
    int loc[10];
    int s = 0;
#pragma unroll
    for (int j = 0; j < 10; j++) {
        int v = sc[base + j];
        loc[j] = s;
        s += v;
    }
    int x = s;
#pragma unroll
    for (int o = 1; o < 32; o <<= 1) {
        int t2 = __shfl_up_sync(0xFFFFFFFFu, x, o);
        if (lane >= o) x += t2;
    }
    if (lane == 31) warpsum[wid] = x;
    __syncthreads();
    if (wid == 0) {
        int y = warpsum[lane];
#pragma unroll
        for (int o = 1; o < 32; o <<= 1) {
            int t2 = __shfl_up_sync(0xFFFFFFFFu, y, o);
            if (lane >= o) y += t2;
        }
        warpsum[lane] = y;
    }
    __syncthreads();
    int add = (wid > 0) ? warpsum[wid - 1] : 0;
    int excl = x - s + add;
#pragma unroll
    for (int j = 0; j < 10; j++) {
        int i = base + j;
        if (i < n) off[i] = excl + loc[j];
    }
    if (tid == 1023) off[n] = excl + s;
}

__global__ void scatter2_kernel(const int* __restrict__ src0, const int* __restrict__ dst0,
                                const int* __restrict__ off0, const int* __restrict__ rk0,
                                int* __restrict__ csr0,
                                const int* __restrict__ src1, const int* __restrict__ dst1,
                                const int* __restrict__ off1, const int* __restrict__ rk1,
                                int* __restrict__ csr1, int E) {
    int t = blockIdx.x * blockDim.x + threadIdx.x;
    if (t < E) {
        csr0[off0[dst0[t]] + rk0[t]] = src0[t];
    } else if (t < 2 * E) {
        int e = t - E;
        csr1[off1[dst1[e]] + rk1[e]] = src1[e];
    }
}

// ---------------- repack plain weights -> tf32 fragment layout ----------------
__global__ void repack_kernel(RepBatch rb) {
    RepArgs ra = rb.r[blockIdx.y];
    int t = blockIdx.x * 256 + threadIdx.x;
    if (t >= ra.K * HID) return;
    int k = t >> 7, n = t & 127;
    ra.P[packB_idx(k, n)] = to_tf32(ra.W[k * HID + n]);
}

// ---------------- fold arel/mrel into projections, write packed tf32 (x8) ----------------
__global__ void fold_kernel(FoldBatch fb) {
    FoldArgs fa = fb.f[blockIdx.y];
    int t = blockIdx.x * blockDim.x + threadIdx.x;
    if (t >= HID * HID) return;
    int row = t >> 7;
    int col = t & 127;
    int h = col >> 4;
    int eo = col & 15;
    const float* relh = fa.rel + h * (DH * DH);
    const float* wrow = fa.W + row * HID + h * DH;
    float acc = 0.f;
#pragma unroll
    for (int d = 0; d < DH; d++) acc = fmaf(wrow[d], relh[d * DH + eo], acc);
    fa.Pf[packB_idx(row, col)] = to_tf32(acc);
    if (row == 0) {
        const float* brow = fa.b + h * DH;
        float accb = 0.f;
#pragma unroll
        for (int d = 0; d < DH; d++) accb = fmaf(brow[d], relh[d * DH + eo], accb);
        fa.bf[col] = accb;
    }
}

// ---- MMA pair helper ----
#define MMA_PAIR(ACC0, ACC1, AF, BB) \
    asm volatile("mma.sync.aligned.m16n8k8.row.col.f32.tf32.tf32.f32 " \
                 "{%0,%1,%2,%3}, {%4,%5,%6,%7}, {%8,%9}, {%0,%1,%2,%3};" \
                 : "+f"((ACC0)[0]), "+f"((ACC0)[1]), "+f"((ACC0)[2]), "+f"((ACC0)[3]) \
                 : "r"((AF).x), "r"((AF).y), "r"((AF).z), "r"((AF).w), "r"((BB).x), "r"((BB).y)); \
    asm volatile("mma.sync.aligned.m16n8k8.row.col.f32.tf32.tf32.f32 " \
                 "{%0,%1,%2,%3}, {%4,%5,%6,%7}, {%8,%9}, {%0,%1,%2,%3};" \
                 : "+f"((ACC1)[0]), "+f"((ACC1)[1]), "+f"((ACC1)[2]), "+f"((ACC1)[3]) \
                 : "r"((AF).x), "r"((AF).y), "r"((AF).z), "r"((AF).w), "r"((BB).z), "r"((BB).w));

// ---------------- GEMM: tf32 mma.sync, 64x128 tile, staged A + packed-B cp.async ----------------
__global__ void __launch_bounds__(128, 4) gemm_kernel(GemmBatch batch, int M, int K) {
    GemmArgs ga = batch.g[blockIdx.y];
    const int geluA = ga.geluA;
    const int epi = ga.epi;

    __shared__ unsigned Af[2][2048];   // 8KB  x2
    __shared__ unsigned Bs[2][4096];   // 16KB x2

    const int tid = threadIdx.x;
    const int lane = tid & 31;
    const int w = tid >> 5;
    const int m0 = blockIdx.x * 64;

    float acc[16][4];
#pragma unroll
    for (int i = 0; i < 16; i++)
#pragma unroll
        for (int j = 0; j < 4; j++) acc[i][j] = 0.f;

    const int nchunks = K >> 5;
    const int sa_row = tid >> 1;
    const int sa_cb = (tid & 1) << 4;
    const int sa_mtile = sa_row >> 4;
    const int sa_mr = sa_row & 15;

    unsigned sB0 = (unsigned)__cvta_generic_to_shared(&Bs[0][0]) + tid * 16;
    unsigned sB1 = (unsigned)__cvta_generic_to_shared(&Bs[1][0]) + tid * 16;
#define CPB(BUF, CH) do { \
        unsigned sb_ = (BUF) ? sB1 : sB0; \
        const uint4* gp_ = (const uint4*)(ga.B + (size_t)(CH) * 4096) + tid; \
        _Pragma("unroll") \
        for (int j_ = 0; j_ < 8; j_++) \
            asm volatile("cp.async.ca.shared.global [%0], [%1], 16;" \
                         :: "r"(sb_ + j_ * 2048), "l"(gp_ + j_ * 128) : "memory"); \
        asm volatile("cp.async.commit_group;" ::: "memory"); \
    } while (0)

    CPB(0, 0);

    for (int ch = 0; ch < nchunks; ch++) {
        int cur = ch & 1;
        // ---- stage A (64 x 32), optional gelu, tf32, fragment-shuffled ----
        {
            int grow = m0 + sa_row;
            const float* ap = ga.A + (size_t)grow * K + ch * 32 + sa_cb;
            bool ok = (grow < M);
#pragma unroll
            for (int q = 0; q < 4; q++) {
                float4 v = ok ? *(const float4*)(ap + q * 4) : make_float4(0.f, 0.f, 0.f, 0.f);
                if (geluA && ok) {
                    v.x = gelu_tanh(v.x); v.y = gelu_tanh(v.y);
                    v.z = gelu_tanh(v.z); v.w = gelu_tanh(v.w);
                }
                float fv[4] = {v.x, v.y, v.z, v.w};
#pragma unroll
                for (int e = 0; e < 4; e++) {
                    int c = sa_cb + q * 4 + e;
                    int kstep = c >> 3, kc = c & 7;
                    int fl = ((sa_mr & 7) << 2) + (kc & 3);
                    int reg = (sa_mr >> 3) + ((kc >> 2) << 1);
                    Af[cur][(((kstep << 2) + sa_mtile) * 32 + fl) * 4 + reg] = to_tf32(fv[e]);
                }
            }
        }
        if (ch + 1 < nchunks) {
            CPB(cur ^ 1, ch + 1);
            asm volatile("cp.async.wait_group 1;" ::: "memory");
        } else {
            asm volatile("cp.async.wait_group 0;" ::: "memory");
        }
        __syncthreads();

        // ---- compute: 4 k-steps x 8 nt-pairs ----
#pragma unroll
        for (int ks = 0; ks < 4; ks++) {
            uint4 af = *(const uint4*)&Af[cur][(((ks << 2) + w) * 32 + lane) * 4];
#pragma unroll
            for (int ntp = 0; ntp < 8; ntp++) {
                uint4 bb = *(const uint4*)&Bs[cur][((ks * 8 + ntp) * 32 + lane) * 4];
                MMA_PAIR(acc[2 * ntp], acc[2 * ntp + 1], af, bb);
            }
        }
        __syncthreads();
    }
#undef CPB

    // ---- epilogue ----
    const int gid = lane >> 2;
    const int tq = lane & 3;
    const int row0 = m0 + w * 16 + gid;
    float sg = 0.f;
    if (epi == 2) sg = 1.f / (1.f + __expf(-ga.skipp[0]));

#pragma unroll
    for (int nt = 0; nt < 16; nt++) {
        int n = nt * 8 + tq * 2;
        float b0v = ga.bias[n];
        float b1v = ga.bias[n + 1];
#pragma unroll
        for (int rsel = 0; rsel < 2; rsel++) {
            int row = row0 + rsel * 8;
            if (row >= M) continue;
            float o0 = acc[nt][rsel * 2 + 0] + b0v;
            float o1 = acc[nt][rsel * 2 + 1] + b1v;
            if (epi == 1) { o0 = fmaxf(o0, 0.f); o1 = fmaxf(o1, 0.f); }
            if (epi == 3) {
                __half* cp = (__half*)ga.C + (size_t)row * 256 + ((n >> 2) << 3) + (n & 3) + ga.cofs;
                *(__half2*)cp = __floats2half2_rn(o0, o1);
            } else {
                float* cp = (float*)ga.C + (size_t)row * HID + n;
                if (epi == 2) {
                    float2 hp = *(const float2*)(ga.Hprev + (size_t)row * HID + n);
                    o0 = sg * o0 + (1.f - sg) * hp.x;
                    o1 = sg * o1 + (1.f - sg) * hp.y;
                }
                *(float2*)cp = make_float2(o0, o1);
            }
        }
    }
}

// ---------------- attention: warp/dst, online softmax, interleaved fp16 kv ----------------
__device__ __forceinline__ void ld_kv8(const __half* kvbase, int lane, float* k4, float* v4) {
    uint4 u = ((const uint4*)kvbase)[lane];
    float2 a = __half22float2(*(__half2*)&u.x);
    float2 b = __half22float2(*(__half2*)&u.y);
    float2 c = __half22float2(*(__half2*)&u.z);
    float2 d = __half22float2(*(__half2*)&u.w);
    k4[0] = a.x; k4[1] = a.y; k4[2] = b.x; k4[3] = b.y;
    v4[0] = c.x; v4[1] = c.y; v4[2] = d.x; v4[3] = d.y;
}

__global__ void __launch_bounds__(256) attn_kernel(AttnBatch ab, int n) {
    AttnArgs aa = ab.a[blockIdx.y];
    int node = blockIdx.x * 8 + (threadIdx.x >> 5);
    if (node >= n) return;
    int lane = threadIdx.x & 31;
    int h = lane >> 2;

    int beg = aa.off[node];
    int end = aa.off[node + 1];
    float4 qv = ((const float4*)(aa.q + (size_t)node * HID))[lane];
    float pr = aa.prior[h] * 0.25f;  // 1/sqrt(16)

    float m = -INFINITY, s = 0.f;
    float ax = 0.f, ay = 0.f, az = 0.f, aw = 0.f;

    int i = beg;
    for (; i + 3 < end; i += 4) {
        int sn0 = aa.csr[i], sn1 = aa.csr[i + 1], sn2 = aa.csr[i + 2], sn3 = aa.csr[i + 3];
        float kf[4][4], vf[4][4];
        ld_kv8(aa.kv + (size_t)sn0 * 256, lane, kf[0], vf[0]);
        ld_kv8(aa.kv + (size_t)sn1 * 256, lane, kf[1], vf[1]);
        ld_kv8(aa.kv + (size_t)sn2 * 256, lane, kf[2], vf[2]);
        ld_kv8(aa.kv + (size_t)sn3 * 256, lane, kf[3], vf[3]);
        float d[4];
#pragma unroll
        for (int j = 0; j < 4; j++)
            d[j] = qv.x * kf[j][0] + qv.y * kf[j][1] + qv.z * kf[j][2] + qv.w * kf[j][3];
#pragma unroll
        for (int j = 0; j < 4; j++) d[j] += __shfl_xor_sync(0xFFFFFFFFu, d[j], 1);
#pragma unroll
        for (int j = 0; j < 4; j++) d[j] += __shfl_xor_sync(0xFFFFFFFFu, d[j], 2);
        float lg0 = d[0] * pr, lg1 = d[1] * pr, lg2 = d[2] * pr, lg3 = d[3] * pr;
        float nm = fmaxf(fmaxf(m, fmaxf(lg0, lg1)), fmaxf(lg2, lg3));
        float c = __expf(m - nm);
        float w0 = __expf(lg0 - nm);
        float w1 = __expf(lg1 - nm);
        float w2 = __expf(lg2 - nm);
        float w3 = __expf(lg3 - nm);
        m = nm;
        s = s * c + w0 + w1 + w2 + w3;
        ax = ax * c + w0 * vf[0][0] + w1 * vf[1][0] + w2 * vf[2][0] + w3 * vf[3][0];
        ay = ay * c + w0 * vf[0][1] + w1 * vf[1][1] + w2 * vf[2][1] + w3 * vf[3][1];
        az = az * c + w0 * vf[0][2] + w1 * vf[1][2] + w2 * vf[2][2] + w3 * vf[3][2];
        aw = aw * c + w0 * vf[0][3] + w1 * vf[1][3] + w2 * vf[2][3] + w3 * vf[3][3];
    }
    for (; i < end; i++) {
        int sn = aa.csr[i];
        float kv[4], vv[4];
        ld_kv8(aa.kv + (size_t)sn * 256, lane, kv, vv);
        float d = qv.x * kv[0] + qv.y * kv[1] + qv.z * kv[2] + qv.w * kv[3];
        d += __shfl_xor_sync(0xFFFFFFFFu, d, 1);
        d += __shfl_xor_sync(0xFFFFFFFFu, d, 2);
        float lg = d * pr;
        float nm = fmaxf(m, lg);
        float c = __expf(m - nm);
        float w = __expf(lg - nm);
        m = nm;
        s = s * c + w;
        ax = ax * c + w * vv[0];
        ay = ay * c + w * vv[1];
        az = az * c + w * vv[2];
        aw = aw * c + w * vv[3];
    }
    float inv = 1.f / (s + 1e-16f);
    ((float4*)(aa.agg + (size_t)node * HID))[lane] = make_float4(ax * inv, ay * inv, az * inv, aw * inv);
}

// ---------------- pair scoring ----------------
__global__ void pred_kernel(const float* __restrict__ f1a, const float* __restrict__ f1b,
                            const float* __restrict__ f2a, const float* __restrict__ f2b,
                            const int* __restrict__ mi, const int* __restrict__ di,
                            float* __restrict__ out, int P) {
    int gw = (blockIdx.x * blockDim.x + threadIdx.x) >> 5;
    int lane = threadIdx.x & 31;
    if (gw >= P) return;
    int mm = mi[gw];
    int dd = di[gw];
    float4 a0 = ((const float4*)(f1a + (size_t)mm * HID))[lane];
    float4 b0 = ((const float4*)(f2a + (size_t)dd * HID))[lane];
    float4 a1 = ((const float4*)(f1b + (size_t)mm * HID))[lane];
    float4 b1 = ((const float4*)(f2b + (size_t)dd * HID))[lane];
    float acc = a0.x * b0.x + a0.y * b0.y + a0.z * b0.z + a0.w * b0.w
              + a1.x * b1.x + a1.y * b1.y + a1.z * b1.z + a1.w * b1.w;
#pragma unroll
    for (int o = 16; o > 0; o >>= 1) acc += __shfl_xor_sync(0xFFFFFFFFu, acc, o);
    if (lane == 0) out[gw] = acc;
}

// ---------------- host orchestration ----------------
extern "C" void kernel_launch(void* const* d_in, const int* in_sizes, int n_in,
                              void* d_out, int out_size) {
    const float* x1    = (const float*)d_in[0];
    const float* x2    = (const float*)d_in[1];
    const int*   ei12  = (const int*)d_in[2];
    const int*   ei21  = (const int*)d_in[3];
    const int*   epair = (const int*)d_in[4];
    const float* Win1  = (const float*)d_in[5];
    const float* bin1  = (const float*)d_in[6];
    const float* Win2  = (const float*)d_in[7];
    const float* bin2  = (const float*)d_in[8];
    const float* Wk    = (const float*)d_in[9];
    const float* bk    = (const float*)d_in[10];
    const float* Wq    = (const float*)d_in[11];
    const float* bq    = (const float*)d_in[12];
    const float* Wv    = (const float*)d_in[13];
    const float* bv    = (const float*)d_in[14];
    const float* Wa    = (const float*)d_in[15];
    const float* ba    = (const float*)d_in[16];
    const float* skip  = (const float*)d_in[17];
    const float* arel  = (const float*)d_in[18];
    const float* mrel  = (const float*)d_in[19];
    const float* prior = (const float*)d_in[20];
    float* out = (float*)d_out;

    void* p;
#define SYMF(var, sym) cudaGetSymbolAddress(&p, sym); float* var = (float*)p;
#define SYMH(var, sym) cudaGetSymbolAddress(&p, sym); __half* var = (__half*)p;
#define SYMI(var, sym) cudaGetSymbolAddress(&p, sym); int* var = (int*)p;
#define SYMU(var, sym) cudaGetSymbolAddress(&p, sym); unsigned* var = (unsigned*)p;
    SYMF(h1, g_h1) SYMF(h2, g_h2)
    SYMF(q1, g_q1) SYMF(q2, g_q2)
    SYMH(kv1, g_kv1) SYMH(kv2, g_kv2)
    SYMF(f1, g_f1) SYMF(f2, g_f2)
    SYMF(agg1, g_agg1) SYMF(agg2, g_agg2)
    SYMF(bfbase, g_bf)
    SYMU(pWin, g_pWin) SYMU(pQA, g_pQA) SYMU(pWf, g_pWf)
    SYMI(cnt, g_cnt) SYMI(off, g_off) SYMI(rnk, g_rank) SYMI(csr, g_csr_src)
#undef SYMF
#undef SYMH
#undef SYMI
#undef SYMU
    float* bf[8];
    unsigned* wfp[8];
    for (int i = 0; i < 8; i++) { wfp[i] = pWf + (size_t)i * HID * HID; bf[i] = bfbase + i * HID; }
    int* cnt12 = cnt;  int* cnt21 = cnt + N1;
    int* off12 = off;  int* off21 = off + (N1 + 1);
    int* rk12 = rnk;   int* rk21 = rnk + E_EDGES;
    int* csr12 = csr;  int* csr21 = csr + E_EDGES;

    const int GEMM_GRID = (N1 + 63) / 64;     // 157
    const int E2_BLOCKS = (2 * E_EDGES + 255) / 256;
    const int ATTN_GRID = (N1 + 7) / 8;
    const int PRED_BLOCKS = (P_PAIRS * 32 + 255) / 256;

    // ---- repack static weights ----
    {
        RepBatch rb;
        rb.r[0] = {Win1, pWin, F_IN};
        rb.r[1] = {Win2, pWin + F_IN * HID, F_IN};
        for (int l = 0; l < 2; l++) {
            rb.r[2 + l * 4 + 0] = {Wq + (size_t)(l * 2 + 0) * HID * HID, pQA + (size_t)(l * 4 + 0) * HID * HID, HID};
            rb.r[2 + l * 4 + 1] = {Wq + (size_t)(l * 2 + 1) * HID * HID, pQA + (size_t)(l * 4 + 1) * HID * HID, HID};
            rb.r[2 + l * 4 + 2] = {Wa + (size_t)(l * 2 + 0) * HID * HID, pQA + (size_t)(l * 4 + 2) * HID * HID, HID};
            rb.r[2 + l * 4 + 3] = {Wa + (size_t)(l * 2 + 1) * HID * HID, pQA + (size_t)(l * 4 + 3) * HID * HID, HID};
        }
        repack_kernel<<<dim3(128, 10), 256>>>(rb);
    }

    // ---- fold both layers' K/V relation weights ----
    {
        FoldBatch fb;
        for (int l = 0; l < 2; l++) {
            const int i0 = l * 2 + 0, i1 = l * 2 + 1;
            fb.f[l * 4 + 0] = {Wk + (size_t)i0 * HID * HID, bk + (size_t)i0 * HID,
                               arel + (size_t)i0 * NHEAD * DH * DH, wfp[l * 4 + 0], bf[l * 4 + 0]};
            fb.f[l * 4 + 1] = {Wk + (size_t)i1 * HID * HID, bk + (size_t)i1 * HID,
                               arel + (size_t)i1 * NHEAD * DH * DH, wfp[l * 4 + 1], bf[l * 4 + 1]};
            fb.f[l * 4 + 2] = {Wv + (size_t)i0 * HID * HID, bv + (size_t)i0 * HID,
                               mrel + (size_t)i0 * NHEAD * DH * DH, wfp[l * 4 + 2], bf[l * 4 + 2]};
            fb.f[l * 4 + 3] = {Wv + (size_t)i1 * HID * HID, bv + (size_t)i1 * HID,
                               mrel + (size_t)i1 * NHEAD * DH * DH, wfp[l * 4 + 3], bf[l * 4 + 3]};
        }
        fold_kernel<<<dim3(64, 8), 256>>>(fb);
    }

    // ---- CSR build ----
    cudaMemsetAsync(cnt12, 0, (size_t)2 * N1 * 4);
    hist2_kernel<<<E2_BLOCKS, 256>>>(ei12 + E_EDGES, cnt12, rk12,
                                     ei21 + E_EDGES, cnt21, rk21, E_EDGES);
    scan2_kernel<<<2, 1024>>>(cnt12, off12, cnt21, off21, N1);
    scatter2_kernel<<<E2_BLOCKS, 256>>>(ei12, ei12 + E_EDGES, off12, rk12, csr12,
                                        ei21, ei21 + E_EDGES, off21, rk21, csr21, E_EDGES);

    // ---- input projections + relu ----
    {
        GemmBatch gb = {};
        gb.g[0] = {x1, pWin, bin1, nullptr, nullptr, h1, 0, 1, 0};
        gb.g[1] = {x2, pWin + F_IN * HID, bin2, nullptr, nullptr, h2, 0, 1, 0};
        gemm_kernel<<<dim3(GEMM_GRID, 2), 128>>>(gb, N1, F_IN);
    }

    const float* cur1 = h1;
    const float* cur2 = h2;

    for (int l = 0; l < 2; l++) {
        const int i0 = l * 2 + 0, i1 = l * 2 + 1;
        {
            GemmBatch gb;
            gb.g[0] = {cur1, pQA + (size_t)(l * 4 + 0) * HID * HID, bq + (size_t)i0 * HID, nullptr, nullptr, q1, 0, 0, 0};
            gb.g[1] = {cur2, pQA + (size_t)(l * 4 + 1) * HID * HID, bq + (size_t)i1 * HID, nullptr, nullptr, q2, 0, 0, 0};
            gb.g[2] = {cur1, wfp[l * 4 + 0], bf[l * 4 + 0], nullptr, nullptr, kv1, 0, 3, 0};
            gb.g[3] = {cur2, wfp[l * 4 + 1], bf[l * 4 + 1], nullptr, nullptr, kv2, 0, 3, 0};
            gb.g[4] = {cur1, wfp[l * 4 + 2], bf[l * 4 + 2], nullptr, nullptr, kv1, 0, 3, 4};
            gb.g[5] = {cur2, wfp[l * 4 + 3], bf[l * 4 + 3], nullptr, nullptr, kv2, 0, 3, 4};
            gemm_kernel<<<dim3(GEMM_GRID, 6), 128>>>(gb, N1, HID);
        }
        {
            AttnBatch ab;
            ab.a[0] = {q2, kv1, csr12, off12, prior + i0 * NHEAD, agg2};
            ab.a[1] = {q1, kv2, csr21, off21, prior + i1 * NHEAD, agg1};
            attn_kernel<<<dim3(ATTN_GRID, 2), 256>>>(ab, N1);
        }
        float* out1 = f1 + (size_t)l * N1 * HID;
        float* out2 = f2 + (size_t)l * N2 * HID;
        {
            GemmBatch gb = {};
            gb.g[0] = {agg1, pQA + (size_t)(l * 4 + 2) * HID * HID, ba + (size_t)i0 * HID, cur1, skip + i0, out1, 1, 2, 0};
            gb.g[1] = {agg2, pQA + (size_t)(l * 4 + 3) * HID * HID, ba + (size_t)i1 * HID, cur2, skip + i1, out2, 1, 2, 0};
            gemm_kernel<<<dim3(GEMM_GRID, 2), 128>>>(gb, N1, HID);
        }
        cur1 = out1;
        cur2 = out2;
    }

    pred_kernel<<<PRED_BLOCKS, 256>>>(f1, f1 + (size_t)N1 * HID,
                                      f2, f2 + (size_t)N2 * HID,
                                      epair, epair + P_PAIRS, out, P_PAIRS);
}

// round 14
// speedup vs baseline: 1.1497x; 1.0685x over previous
#include <cuda_runtime.h>
#include <cuda_fp16.h>
#include <math.h>

#define N1 10000
#define N2 10000
#define F_IN 256
#define E_EDGES 480000
#define P_PAIRS 200000
#define HID 128
#define NHEAD 8
#define DH 16

// ---------------- scratch (device globals) ----------------
__device__ float g_h1[N1 * HID];
__device__ float g_h2[N2 * HID];
__device__ float g_q1[N1 * HID];
__device__ float g_q2[N2 * HID];
__device__ __half g_kv1[N1 * 2 * HID];
__device__ __half g_kv2[N2 * 2 * HID];
__device__ float g_f1[2 * N1 * HID];
__device__ float g_f2[2 * N2 * HID];
__device__ float g_agg1[N1 * HID];
__device__ float g_agg2[N2 * HID];
__device__ float g_bf[8][HID];
__device__ unsigned g_pWin[2][F_IN * HID];
__device__ unsigned g_pQA[8][HID * HID];
__device__ unsigned g_pWf[8][HID * HID];
__device__ int g_cnt[2][N1];
__device__ int g_off[2][N1 + 1];
__device__ int g_rank[2][E_EDGES];
__device__ int g_csr_src[2][E_EDGES];

// ---------------- arg structs ----------------
struct GemmArgs { const float* A; const unsigned* B; const float* bias;
                  const float* Hprev; const float* skipp; void* C;
                  int geluA; int epi; int cofs; };
struct GemmBatch { GemmArgs g[6]; };
struct FoldArgs { const float* W; const float* b; const float* rel; unsigned* Pf; float* bf; };
struct RepArgs { const float* W; unsigned* P; int K; };
struct PrepBatch { RepArgs r[10]; FoldArgs f[8]; };
struct AttnArgs { const float* q; const __half* kv;
                  const int* csr; const int* off; const float* prior; float* agg; };
struct AttnBatch { AttnArgs a[2]; };

__device__ __forceinline__ float gelu_tanh(float x) {
    const float c = 0.7978845608028654f;
    float t = tanhf(c * (x + 0.044715f * x * x * x));
    return 0.5f * x * (1.0f + t);
}

__device__ __forceinline__ unsigned to_tf32(float f) {
    unsigned u;
    asm("cvt.rna.tf32.f32 %0, %1;" : "=r"(u) : "f"(f));
    return u;
}

// packed B fragment index (value at k,n)
__device__ __forceinline__ int packB_idx(int k, int n) {
    int ch = k >> 5, k32 = k & 31;
    int ks = k32 >> 3, kr = k32 & 7;
    int reg = kr >> 2;
    int lane = ((n & 7) << 2) | (kr & 3);
    int nt = n >> 3, ntp = nt >> 1, ntl = nt & 1;
    int q = ntl * 2 + reg;
    return ch * 4096 + ((ks * 8 + ntp) * 32 + lane) * 4 + q;
}

// ---------------- CSR build ----------------
__global__ void hist2_kernel(const int* __restrict__ dst0, int* __restrict__ cnt0, int* __restrict__ rk0,
                             const int* __restrict__ dst1, int* __restrict__ cnt1, int* __restrict__ rk1,
                             int E) {
    int t = blockIdx.x * blockDim.x + threadIdx.x;
    if (t < E) rk0[t] = atomicAdd(cnt0 + dst0[t], 1);
    else if (t < 2 * E) rk1[t - E] = atomicAdd(cnt1 + dst1[t - E], 1);
}

// thread-coarsened single-pass scan with coalesced smem staging (n <= 10240)
__global__ void scan2_kernel(const int* __restrict__ cnt0, int* __restrict__ off0,
                             const int* __restrict__ cnt1, int* __restrict__ off1, int n) {
    const int* cnt = blockIdx.x ? cnt1 : cnt0;
    int* off = blockIdx.x ? off1 : off0;
    __shared__ int sc[10240];
    __shared__ int warpsum[32];
    int tid = threadIdx.x, lane = tid & 31, wid = tid >> 5;
    const int4* c4 = (const int4*)cnt;
#pragma unroll
    for (int j = 0; j < 3; j++) {
        int i = tid + j * 1024;
        if (i < 2500) ((int4*)sc)[i] = c4[i];
    }
    if (tid >= 784 && tid < 1024) sc[10000 + (tid - 784)] = 0;
    __syncthreads();

    int base = tid * 10;
    int loc[10];
    int s = 0;
#pragma unroll
    for (int j = 0; j < 10; j++) {
        int v = sc[base + j];
        loc[j] = s;
        s += v;
    }
    int x = s;
#pragma unroll
    for (int o = 1; o < 32; o <<= 1) {
        int t2 = __shfl_up_sync(0xFFFFFFFFu, x, o);
        if (lane >= o) x += t2;
    }
    if (lane == 31) warpsum[wid] = x;
    __syncthreads();
    if (wid == 0) {
        int y = warpsum[lane];
#pragma unroll
        for (int o = 1; o < 32; o <<= 1) {
            int t2 = __shfl_up_sync(0xFFFFFFFFu, y, o);
            if (lane >= o) y += t2;
        }
        warpsum[lane] = y;
    }
    __syncthreads();
    int add = (wid > 0) ? warpsum[wid - 1] : 0;
    int excl = x - s + add;
#pragma unroll
    for (int j = 0; j < 10; j++) {
        int i = base + j;
        if (i < n) off[i] = excl + loc[j];
    }
    if (tid == 1023) off[n] = excl + s;
}

__global__ void scatter2_kernel(const int* __restrict__ src0, const int* __restrict__ dst0,
                                const int* __restrict__ off0, const int* __restrict__ rk0,
                                int* __restrict__ csr0,
                                const int* __restrict__ src1, const int* __restrict__ dst1,
                                const int* __restrict__ off1, const int* __restrict__ rk1,
                                int* __restrict__ csr1, int E) {
    int t = blockIdx.x * blockDim.x + threadIdx.x;
    if (t < E) {
        csr0[off0[dst0[t]] + rk0[t]] = src0[t];
    } else if (t < 2 * E) {
        int e = t - E;
        csr1[off1[dst1[e]] + rk1[e]] = src1[e];
    }
}

// ---------------- merged repack (y 0..9) + fold (y 10..17) ----------------
__global__ void prep_kernel(PrepBatch pb) {
    int y = blockIdx.y;
    int t = blockIdx.x * 256 + threadIdx.x;
    if (y < 10) {
        RepArgs ra = pb.r[y];
        if (t >= ra.K * HID) return;
        int k = t >> 7, n = t & 127;
        ra.P[packB_idx(k, n)] = to_tf32(ra.W[k * HID + n]);
    } else {
        FoldArgs fa = pb.f[y - 10];
        if (t >= HID * HID) return;
        int row = t >> 7;
        int col = t & 127;
        int h = col >> 4;
        int eo = col & 15;
        const float* relh = fa.rel + h * (DH * DH);
        const float* wrow = fa.W + row * HID + h * DH;
        float acc = 0.f;
#pragma unroll
        for (int d = 0; d < DH; d++) acc = fmaf(wrow[d], relh[d * DH + eo], acc);
        fa.Pf[packB_idx(row, col)] = to_tf32(acc);
        if (row == 0) {
            const float* brow = fa.b + h * DH;
            float accb = 0.f;
#pragma unroll
            for (int d = 0; d < DH; d++) accb = fmaf(brow[d], relh[d * DH + eo], accb);
            fa.bf[col] = accb;
        }
    }
}

// ---- MMA pair helper ----
#define MMA_PAIR(ACC0, ACC1, AF, BB) \
    asm volatile("mma.sync.aligned.m16n8k8.row.col.f32.tf32.tf32.f32 " \
                 "{%0,%1,%2,%3}, {%4,%5,%6,%7}, {%8,%9}, {%0,%1,%2,%3};" \
                 : "+f"((ACC0)[0]), "+f"((ACC0)[1]), "+f"((ACC0)[2]), "+f"((ACC0)[3]) \
                 : "r"((AF).x), "r"((AF).y), "r"((AF).z), "r"((AF).w), "r"((BB).x), "r"((BB).y)); \
    asm volatile("mma.sync.aligned.m16n8k8.row.col.f32.tf32.tf32.f32 " \
                 "{%0,%1,%2,%3}, {%4,%5,%6,%7}, {%8,%9}, {%0,%1,%2,%3};" \
                 : "+f"((ACC1)[0]), "+f"((ACC1)[1]), "+f"((ACC1)[2]), "+f"((ACC1)[3]) \
                 : "r"((AF).x), "r"((AF).y), "r"((AF).z), "r"((AF).w), "r"((BB).z), "r"((BB).w));

// ---------------- GEMM: tf32 mma.sync, 64x128 tile ----------------
// A fragment smem layout: [kstep][mtile][reg][lane] -> staging is STS.128, raw fp32 bits as tf32.
__global__ void __launch_bounds__(128, 4) gemm_kernel(GemmBatch batch, int M, int K) {
    GemmArgs ga = batch.g[blockIdx.y];
    const int geluA = ga.geluA;
    const int epi = ga.epi;

    __shared__ unsigned Af[2][2048];   // 8KB  x2  : ((kstep*4+mtile)*4+reg)*32 + lane
    __shared__ unsigned Bs[2][4096];   // 16KB x2

    const int tid = threadIdx.x;
    const int lane = tid & 31;
    const int w = tid >> 5;
    const int m0 = blockIdx.x * 64;

    float acc[16][4];
#pragma unroll
    for (int i = 0; i < 16; i++)
#pragma unroll
        for (int j = 0; j < 4; j++) acc[i][j] = 0.f;

    const int nchunks = K >> 5;
    const int sa_row = tid >> 1;           // 0..63
    const int sa_cb = (tid & 1) << 4;      // 0 or 16
    const int sa_mtile = sa_row >> 4;
    const int sa_mr = sa_row & 15;
    const int sa_fl4 = (sa_mr & 7) << 2;
    const int sa_regbase = sa_mr >> 3;

    unsigned sB0 = (unsigned)__cvta_generic_to_shared(&Bs[0][0]) + tid * 16;
    unsigned sB1 = (unsigned)__cvta_generic_to_shared(&Bs[1][0]) + tid * 16;
#define CPB(BUF, CH) do { \
        unsigned sb_ = (BUF) ? sB1 : sB0; \
        const uint4* gp_ = (const uint4*)(ga.B + (size_t)(CH) * 4096) + tid; \
        _Pragma("unroll") \
        for (int j_ = 0; j_ < 8; j_++) \
            asm volatile("cp.async.ca.shared.global [%0], [%1], 16;" \
                         :: "r"(sb_ + j_ * 2048), "l"(gp_ + j_ * 128) : "memory"); \
        asm volatile("cp.async.commit_group;" ::: "memory"); \
    } while (0)

    CPB(0, 0);

    for (int ch = 0; ch < nchunks; ch++) {
        int cur = ch & 1;
        // ---- stage A (64 x 32): 4 x (LDG.128 -> [gelu] -> STS.128), raw bits as tf32 ----
        {
            int grow = m0 + sa_row;
            const float* ap = ga.A + (size_t)grow * K + ch * 32 + sa_cb;
            bool ok = (grow < M);
#pragma unroll
            for (int q = 0; q < 4; q++) {
                float4 v = ok ? *(const float4*)(ap + q * 4) : make_float4(0.f, 0.f, 0.f, 0.f);
                if (geluA && ok) {
                    v.x = gelu_tanh(v.x); v.y = gelu_tanh(v.y);
                    v.z = gelu_tanh(v.z); v.w = gelu_tanh(v.w);
                }
                int c = sa_cb + (q << 2);
                int kstep = c >> 3;
                int reg = sa_regbase + (((c >> 2) & 1) << 1);
                *(float4*)&Af[cur][((((kstep << 2) + sa_mtile) << 2) + reg) * 32 + sa_fl4] = v;
            }
        }
        if (ch + 1 < nchunks) {
            CPB(cur ^ 1, ch + 1);
            asm volatile("cp.async.wait_group 1;" ::: "memory");
        } else {
            asm volatile("cp.async.wait_group 0;" ::: "memory");
        }
        __syncthreads();

        // ---- compute ----
#pragma unroll
        for (int ks = 0; ks < 4; ks++) {
            const unsigned* abase = &Af[cur][(((ks << 2) + w) << 2) * 32 + lane];
            uint4 af;
            af.x = abase[0];
            af.y = abase[32];
            af.z = abase[64];
            af.w = abase[96];
#pragma unroll
            for (int ntp = 0; ntp < 8; ntp++) {
                uint4 bb = *(const uint4*)&Bs[cur][((ks * 8 + ntp) * 32 + lane) * 4];
                MMA_PAIR(acc[2 * ntp], acc[2 * ntp + 1], af, bb);
            }
        }
        __syncthreads();
    }
#undef CPB

    // ---- epilogue ----
    const int gid = lane >> 2;
    const int tq = lane & 3;
    const int row0 = m0 + w * 16 + gid;
    float sg = 0.f;
    if (epi == 2) sg = 1.f / (1.f + __expf(-ga.skipp[0]));

#pragma unroll
    for (int nt = 0; nt < 16; nt++) {
        int n = nt * 8 + tq * 2;
        float b0v = ga.bias[n];
        float b1v = ga.bias[n + 1];
#pragma unroll
        for (int rsel = 0; rsel < 2; rsel++) {
            int row = row0 + rsel * 8;
            if (row >= M) continue;
            float o0 = acc[nt][rsel * 2 + 0] + b0v;
            float o1 = acc[nt][rsel * 2 + 1] + b1v;
            if (epi == 1) { o0 = fmaxf(o0, 0.f); o1 = fmaxf(o1, 0.f); }
            if (epi == 3) {
                __half* cp = (__half*)ga.C + (size_t)row * 256 + ((n >> 2) << 3) + (n & 3) + ga.cofs;
                *(__half2*)cp = __floats2half2_rn(o0, o1);
            } else {
                float* cp = (float*)ga.C + (size_t)row * HID + n;
                if (epi == 2) {
                    float2 hp = *(const float2*)(ga.Hprev + (size_t)row * HID + n);
                    o0 = sg * o0 + (1.f - sg) * hp.x;
                    o1 = sg * o1 + (1.f - sg) * hp.y;
                }
                *(float2*)cp = make_float2(o0, o1);
            }
        }
    }
}

// ---------------- attention: warp/dst, online softmax, interleaved fp16 kv ----------------
__device__ __forceinline__ void ld_kv8(const __half* kvbase, int lane, float* k4, float* v4) {
    uint4 u = ((const uint4*)kvbase)[lane];
    float2 a = __half22float2(*(__half2*)&u.x);
    float2 b = __half22float2(*(__half2*)&u.y);
    float2 c = __half22float2(*(__half2*)&u.z);
    float2 d = __half22float2(*(__half2*)&u.w);
    k4[0] = a.x; k4[1] = a.y; k4[2] = b.x; k4[3] = b.y;
    v4[0] = c.x; v4[1] = c.y; v4[2] = d.x; v4[3] = d.y;
}

__global__ void __launch_bounds__(256) attn_kernel(AttnBatch ab, int n) {
    AttnArgs aa = ab.a[blockIdx.y];
    int node = blockIdx.x * 8 + (threadIdx.x >> 5);
    if (node >= n) return;
    int lane = threadIdx.x & 31;
    int h = lane >> 2;

    int beg = aa.off[node];
    int end = aa.off[node + 1];
    float4 qv = ((const float4*)(aa.q + (size_t)node * HID))[lane];
    float pr = aa.prior[h] * 0.25f;

    float m = -INFINITY, s = 0.f;
    float ax = 0.f, ay = 0.f, az = 0.f, aw = 0.f;

    int i = beg;
    for (; i + 3 < end; i += 4) {
        int sn0 = aa.csr[i], sn1 = aa.csr[i + 1], sn2 = aa.csr[i + 2], sn3 = aa.csr[i + 3];
        float kf[4][4], vf[4][4];
        ld_kv8(aa.kv + (size_t)sn0 * 256, lane, kf[0], vf[0]);
        ld_kv8(aa.kv + (size_t)sn1 * 256, lane, kf[1], vf[1]);
        ld_kv8(aa.kv + (size_t)sn2 * 256, lane, kf[2], vf[2]);
        ld_kv8(aa.kv + (size_t)sn3 * 256, lane, kf[3], vf[3]);
        float d[4];
#pragma unroll
        for (int j = 0; j < 4; j++)
            d[j] = qv.x * kf[j][0] + qv.y * kf[j][1] + qv.z * kf[j][2] + qv.w * kf[j][3];
#pragma unroll
        for (int j = 0; j < 4; j++) d[j] += __shfl_xor_sync(0xFFFFFFFFu, d[j], 1);
#pragma unroll
        for (int j = 0; j < 4; j++) d[j] += __shfl_xor_sync(0xFFFFFFFFu, d[j], 2);
        float lg0 = d[0] * pr, lg1 = d[1] * pr, lg2 = d[2] * pr, lg3 = d[3] * pr;
        float nm = fmaxf(fmaxf(m, fmaxf(lg0, lg1)), fmaxf(lg2, lg3));
        float c = __expf(m - nm);
        float w0 = __expf(lg0 - nm);
        float w1 = __expf(lg1 - nm);
        float w2 = __expf(lg2 - nm);
        float w3 = __expf(lg3 - nm);
        m = nm;
        s = s * c + w0 + w1 + w2 + w3;
        ax = ax * c + w0 * vf[0][0] + w1 * vf[1][0] + w2 * vf[2][0] + w3 * vf[3][0];
        ay = ay * c + w0 * vf[0][1] + w1 * vf[1][1] + w2 * vf[2][1] + w3 * vf[3][1];
        az = az * c + w0 * vf[0][2] + w1 * vf[1][2] + w2 * vf[2][2] + w3 * vf[3][2];
        aw = aw * c + w0 * vf[0][3] + w1 * vf[1][3] + w2 * vf[2][3] + w3 * vf[3][3];
    }
    for (; i < end; i++) {
        int sn = aa.csr[i];
        float kv[4], vv[4];
        ld_kv8(aa.kv + (size_t)sn * 256, lane, kv, vv);
        float d = qv.x * kv[0] + qv.y * kv[1] + qv.z * kv[2] + qv.w * kv[3];
        d += __shfl_xor_sync(0xFFFFFFFFu, d, 1);
        d += __shfl_xor_sync(0xFFFFFFFFu, d, 2);
        float lg = d * pr;
        float nm = fmaxf(m, lg);
        float c = __expf(m - nm);
        float w = __expf(lg - nm);
        m = nm;
        s = s * c + w;
        ax = ax * c + w * vv[0];
        ay = ay * c + w * vv[1];
        az = az * c + w * vv[2];
        aw = aw * c + w * vv[3];
    }
    float inv = 1.f / (s + 1e-16f);
    ((float4*)(aa.agg + (size_t)node * HID))[lane] = make_float4(ax * inv, ay * inv, az * inv, aw * inv);
}

// ---------------- pair scoring ----------------
__global__ void pred_kernel(const float* __restrict__ f1a, const float* __restrict__ f1b,
                            const float* __restrict__ f2a, const float* __restrict__ f2b,
                            const int* __restrict__ mi, const int* __restrict__ di,
                            float* __restrict__ out, int P) {
    int gw = (blockIdx.x * blockDim.x + threadIdx.x) >> 5;
    int lane = threadIdx.x & 31;
    if (gw >= P) return;
    int mm = mi[gw];
    int dd = di[gw];
    float4 a0 = ((const float4*)(f1a + (size_t)mm * HID))[lane];
    float4 b0 = ((const float4*)(f2a + (size_t)dd * HID))[lane];
    float4 a1 = ((const float4*)(f1b + (size_t)mm * HID))[lane];
    float4 b1 = ((const float4*)(f2b + (size_t)dd * HID))[lane];
    float acc = a0.x * b0.x + a0.y * b0.y + a0.z * b0.z + a0.w * b0.w
              + a1.x * b1.x + a1.y * b1.y + a1.z * b1.z + a1.w * b1.w;
#pragma unroll
    for (int o = 16; o > 0; o >>= 1) acc += __shfl_xor_sync(0xFFFFFFFFu, acc, o);
    if (lane == 0) out[gw] = acc;
}

// ---------------- host orchestration ----------------
extern "C" void kernel_launch(void* const* d_in, const int* in_sizes, int n_in,
                              void* d_out, int out_size) {
    const float* x1    = (const float*)d_in[0];
    const float* x2    = (const float*)d_in[1];
    const int*   ei12  = (const int*)d_in[2];
    const int*   ei21  = (const int*)d_in[3];
    const int*   epair = (const int*)d_in[4];
    const float* Win1  = (const float*)d_in[5];
    const float* bin1  = (const float*)d_in[6];
    const float* Win2  = (const float*)d_in[7];
    const float* bin2  = (const float*)d_in[8];
    const float* Wk    = (const float*)d_in[9];
    const float* bk    = (const float*)d_in[10];
    const float* Wq    = (const float*)d_in[11];
    const float* bq    = (const float*)d_in[12];
    const float* Wv    = (const float*)d_in[13];
    const float* bv    = (const float*)d_in[14];
    const float* Wa    = (const float*)d_in[15];
    const float* ba    = (const float*)d_in[16];
    const float* skip  = (const float*)d_in[17];
    const float* arel  = (const float*)d_in[18];
    const float* mrel  = (const float*)d_in[19];
    const float* prior = (const float*)d_in[20];
    float* out = (float*)d_out;

    void* p;
#define SYMF(var, sym) cudaGetSymbolAddress(&p, sym); float* var = (float*)p;
#define SYMH(var, sym) cudaGetSymbolAddress(&p, sym); __half* var = (__half*)p;
#define SYMI(var, sym) cudaGetSymbolAddress(&p, sym); int* var = (int*)p;
#define SYMU(var, sym) cudaGetSymbolAddress(&p, sym); unsigned* var = (unsigned*)p;
    SYMF(h1, g_h1) SYMF(h2, g_h2)
    SYMF(q1, g_q1) SYMF(q2, g_q2)
    SYMH(kv1, g_kv1) SYMH(kv2, g_kv2)
    SYMF(f1, g_f1) SYMF(f2, g_f2)
    SYMF(agg1, g_agg1) SYMF(agg2, g_agg2)
    SYMF(bfbase, g_bf)
    SYMU(pWin, g_pWin) SYMU(pQA, g_pQA) SYMU(pWf, g_pWf)
    SYMI(cnt, g_cnt) SYMI(off, g_off) SYMI(rnk, g_rank) SYMI(csr, g_csr_src)
#undef SYMF
#undef SYMH
#undef SYMI
#undef SYMU
    float* bf[8];
    unsigned* wfp[8];
    for (int i = 0; i < 8; i++) { wfp[i] = pWf + (size_t)i * HID * HID; bf[i] = bfbase + i * HID; }
    int* cnt12 = cnt;  int* cnt21 = cnt + N1;
    int* off12 = off;  int* off21 = off + (N1 + 1);
    int* rk12 = rnk;   int* rk21 = rnk + E_EDGES;
    int* csr12 = csr;  int* csr21 = csr + E_EDGES;

    const int GEMM_GRID = (N1 + 63) / 64;     // 157
    const int E2_BLOCKS = (2 * E_EDGES + 255) / 256;
    const int ATTN_GRID = (N1 + 7) / 8;
    const int PRED_BLOCKS = (P_PAIRS * 32 + 255) / 256;

    // ---- merged repack + fold (one launch) ----
    {
        PrepBatch pb;
        pb.r[0] = {Win1, pWin, F_IN};
        pb.r[1] = {Win2, pWin + F_IN * HID, F_IN};
        for (int l = 0; l < 2; l++) {
            pb.r[2 + l * 4 + 0] = {Wq + (size_t)(l * 2 + 0) * HID * HID, pQA + (size_t)(l * 4 + 0) * HID * HID, HID};
            pb.r[2 + l * 4 + 1] = {Wq + (size_t)(l * 2 + 1) * HID * HID, pQA + (size_t)(l * 4 + 1) * HID * HID, HID};
            pb.r[2 + l * 4 + 2] = {Wa + (size_t)(l * 2 + 0) * HID * HID, pQA + (size_t)(l * 4 + 2) * HID * HID, HID};
            pb.r[2 + l * 4 + 3] = {Wa + (size_t)(l * 2 + 1) * HID * HID, pQA + (size_t)(l * 4 + 3) * HID * HID, HID};
            const int i0 = l * 2 + 0, i1 = l * 2 + 1;
            pb.f[l * 4 + 0] = {Wk + (size_t)i0 * HID * HID, bk + (size_t)i0 * HID,
                               arel + (size_t)i0 * NHEAD * DH * DH, wfp[l * 4 + 0], bf[l * 4 + 0]};
            pb.f[l * 4 + 1] = {Wk + (size_t)i1 * HID * HID, bk + (size_t)i1 * HID,
                               arel + (size_t)i1 * NHEAD * DH * DH, wfp[l * 4 + 1], bf[l * 4 + 1]};
            pb.f[l * 4 + 2] = {Wv + (size_t)i0 * HID * HID, bv + (size_t)i0 * HID,
                               mrel + (size_t)i0 * NHEAD * DH * DH, wfp[l * 4 + 2], bf[l * 4 + 2]};
            pb.f[l * 4 + 3] = {Wv + (size_t)i1 * HID * HID, bv + (size_t)i1 * HID,
                               mrel + (size_t)i1 * NHEAD * DH * DH, wfp[l * 4 + 3], bf[l * 4 + 3]};
        }
        prep_kernel<<<dim3(128, 18), 256>>>(pb);
    }

    // ---- CSR build ----
    cudaMemsetAsync(cnt12, 0, (size_t)2 * N1 * 4);
    hist2_kernel<<<E2_BLOCKS, 256>>>(ei12 + E_EDGES, cnt12, rk12,
                                     ei21 + E_EDGES, cnt21, rk21, E_EDGES);
    scan2_kernel<<<2, 1024>>>(cnt12, off12, cnt21, off21, N1);
    scatter2_kernel<<<E2_BLOCKS, 256>>>(ei12, ei12 + E_EDGES, off12, rk12, csr12,
                                        ei21, ei21 + E_EDGES, off21, rk21, csr21, E_EDGES);

    // ---- input projections + relu ----
    {
        GemmBatch gb = {};
        gb.g[0] = {x1, pWin, bin1, nullptr, nullptr, h1, 0, 1, 0};
        gb.g[1] = {x2, pWin + F_IN * HID, bin2, nullptr, nullptr, h2, 0, 1, 0};
        gemm_kernel<<<dim3(GEMM_GRID, 2), 128>>>(gb, N1, F_IN);
    }

    const float* cur1 = h1;
    const float* cur2 = h2;

    for (int l = 0; l < 2; l++) {
        const int i0 = l * 2 + 0, i1 = l * 2 + 1;
        {
            GemmBatch gb;
            gb.g[0] = {cur1, pQA + (size_t)(l * 4 + 0) * HID * HID, bq + (size_t)i0 * HID, nullptr, nullptr, q1, 0, 0, 0};
            gb.g[1] = {cur2, pQA + (size_t)(l * 4 + 1) * HID * HID, bq + (size_t)i1 * HID, nullptr, nullptr, q2, 0, 0, 0};
            gb.g[2] = {cur1, wfp[l * 4 + 0], bf[l * 4 + 0], nullptr, nullptr, kv1, 0, 3, 0};
            gb.g[3] = {cur2, wfp[l * 4 + 1], bf[l * 4 + 1], nullptr, nullptr, kv2, 0, 3, 0};
            gb.g[4] = {cur1, wfp[l * 4 + 2], bf[l * 4 + 2], nullptr, nullptr, kv1, 0, 3, 4};
            gb.g[5] = {cur2, wfp[l * 4 + 3], bf[l * 4 + 3], nullptr, nullptr, kv2, 0, 3, 4};
            gemm_kernel<<<dim3(GEMM_GRID, 6), 128>>>(gb, N1, HID);
        }
        {
            AttnBatch ab;
            ab.a[0] = {q2, kv1, csr12, off12, prior + i0 * NHEAD, agg2};
            ab.a[1] = {q1, kv2, csr21, off21, prior + i1 * NHEAD, agg1};
            attn_kernel<<<dim3(ATTN_GRID, 2), 256>>>(ab, N1);
        }
        float* out1 = f1 + (size_t)l * N1 * HID;
        float* out2 = f2 + (size_t)l * N2 * HID;
        {
            GemmBatch gb = {};
            gb.g[0] = {agg1, pQA + (size_t)(l * 4 + 2) * HID * HID, ba + (size_t)i0 * HID, cur1, skip + i0, out1, 1, 2, 0};
            gb.g[1] = {agg2, pQA + (size_t)(l * 4 + 3) * HID * HID, ba + (size_t)i1 * HID, cur2, skip + i1, out2, 1, 2, 0};
            gemm_kernel<<<dim3(GEMM_GRID, 2), 128>>>(gb, N1, HID);
        }
        cur1 = out1;
        cur2 = out2;
    }

    pred_kernel<<<PRED_BLOCKS, 256>>>(f1, f1 + (size_t)N1 * HID,
                                      f2, f2 + (size_t)N2 * HID,
                                      epair, epair + P_PAIRS, out, P_PAIRS);
}